// round 2
// baseline (speedup 1.0000x reference)
#include <cuda_runtime.h>

// CIN: 3 interaction layers + sum/fc head.
// y[b,h,d] = relu(bias[h] + sum_{m,n} x0[b,m,d] * hprev[b,n,d] * W[m*N+n, h])
// Layer0: hprev = x (N=32, K=1024). Layers1/2: hprev = prev y[:,128:256,:] (N=128, K=4096).
// f[b,j]: j<128 -> y0[:, :128]; j<256 -> y1[:, :128]; j<512 -> y2 (all 256 rows); summed over d.
// out[b] = f[b,:] @ fc_W + fc_b.

#define BATCH 1024
#define MF    32
#define DD    64
#define HH    256

// Inter-layer activations (device scratch; no allocations allowed).
__device__ float g_y0[BATCH * HH * DD];
__device__ float g_y1[BATCH * HH * DD];
__device__ float g_y2[BATCH * HH * DD];

typedef unsigned long long ull;

__device__ __forceinline__ ull pack2(float a, float b) {
    ull r;
    asm("mov.b64 %0, {%1, %2};" : "=l"(r) : "f"(a), "f"(b));
    return r;
}
__device__ __forceinline__ float2 unpack2(ull v) {
    float2 f;
    asm("mov.b64 {%0, %1}, %2;" : "=f"(f.x), "=f"(f.y) : "l"(v));
    return f;
}
// Packed dual-FMA (Blackwell f32x2 pipe): d = a*b + d, lanewise on 2 floats.
__device__ __forceinline__ void ffma2(ull& d, ull a, ull b) {
    asm("fma.rn.f32x2 %0, %1, %2, %0;" : "+l"(d) : "l"(a), "l"(b));
}

// One CIN layer. Grid: 2048 blocks = (batch b) x (h-segment of 128).
// Block: 128 threads. Block tile: 64(d) x 128(h). Thread tile: 4(d) x 16(h).
// K loop in tiles of KT=16; each K-tile has constant m (16 | N_IN), so
// Z[d,k] = x0[m,d] * h[n0+kk, d] needs only 4 FMULs per k per thread.
template <int LAYER, int N_IN>
__global__ void __launch_bounds__(128) cin_layer(const float* __restrict__ x,
                                                 const float* __restrict__ W,
                                                 const float* __restrict__ bias) {
    constexpr int K  = MF * N_IN;
    constexpr int KT = 16;
    constexpr int NT = K / KT;
    constexpr int HB = 128;

    __shared__ __align__(16) float hs[N_IN * DD];   // h tile for this batch
    __shared__ __align__(16) float ws[KT * HB];     // W K-tile, this h-segment

    const int bx   = blockIdx.x;
    const int b    = bx >> 1;
    const int hseg = (bx & 1) * HB;
    const int t    = threadIdx.x;

    // Stage hprev for this batch into SMEM (contiguous rows of 64 floats).
    const float* hsrc;
    if (LAYER == 0)      hsrc = x    + (size_t)b * (MF * DD);
    else if (LAYER == 1) hsrc = g_y0 + (size_t)b * (HH * DD) + 128 * DD;
    else                 hsrc = g_y1 + (size_t)b * (HH * DD) + 128 * DD;

    for (int i = t; i < (N_IN * DD) / 4; i += 128)
        ((float4*)hs)[i] = ((const float4*)hsrc)[i];

    const int d0 = (t & 15) * 4;    // 4 consecutive d per thread
    const int h0 = (t >> 4) * 16;   // 16 consecutive h per thread (8 packed pairs)

    ull acc[4][8];
#pragma unroll
    for (int i = 0; i < 4; i++)
#pragma unroll
        for (int j = 0; j < 8; j++) acc[i][j] = 0ull;  // bit pattern == (0.f, 0.f)

    const float* xb = x + (size_t)b * (MF * DD);

    for (int tile = 0; tile < NT; tile++) {
        const int k0 = tile * KT;
        const int m  = k0 / N_IN;
        const int n0 = k0 % N_IN;   // whole K-tile shares one m row

        // Load W[k0 .. k0+15][hseg .. hseg+127] into SMEM (512 float4s).
#pragma unroll
        for (int i = 0; i < 4; i++) {
            int idx = t + i * 128;        // 0..511
            int row = idx >> 5;           // 0..15
            int c4  = idx & 31;           // float4 column
            ((float4*)ws)[idx] =
                *(const float4*)(W + (size_t)(k0 + row) * HH + hseg + c4 * 4);
        }
        // x0 column for this tile's m (L1-resident after first touch).
        const float4 xv = *(const float4*)(xb + m * DD + d0);
        __syncthreads();

#pragma unroll
        for (int kk = 0; kk < KT; kk++) {
            const float4 hv = *(const float4*)(hs + (n0 + kk) * DD + d0);
            float zs0 = xv.x * hv.x;
            float zs1 = xv.y * hv.y;
            float zs2 = xv.z * hv.z;
            float zs3 = xv.w * hv.w;
            ull zz[4];
            zz[0] = pack2(zs0, zs0);
            zz[1] = pack2(zs1, zs1);
            zz[2] = pack2(zs2, zs2);
            zz[3] = pack2(zs3, zs3);

            ull wp[8];
            {
                const ulonglong2* wr = (const ulonglong2*)(ws + kk * HB + h0);
                ulonglong2 q0 = wr[0], q1 = wr[1], q2 = wr[2], q3 = wr[3];
                wp[0] = q0.x; wp[1] = q0.y;
                wp[2] = q1.x; wp[3] = q1.y;
                wp[4] = q2.x; wp[5] = q2.y;
                wp[6] = q3.x; wp[7] = q3.y;
            }
#pragma unroll
            for (int i = 0; i < 4; i++)
#pragma unroll
                for (int j = 0; j < 8; j++) ffma2(acc[i][j], zz[i], wp[j]);
        }
        __syncthreads();
    }

    // Epilogue: bias + relu, write y[b][h][d] (d contiguous).
    float* yout = (LAYER == 0 ? g_y0 : LAYER == 1 ? g_y1 : g_y2) + (size_t)b * (HH * DD);
#pragma unroll
    for (int i = 0; i < 4; i++) {
#pragma unroll
        for (int j = 0; j < 8; j++) {
            float2 v = unpack2(acc[i][j]);
            int h = hseg + h0 + 2 * j;
            yout[(size_t)h * DD + d0 + i]       = fmaxf(v.x + bias[h], 0.0f);
            yout[(size_t)(h + 1) * DD + d0 + i] = fmaxf(v.y + bias[h + 1], 0.0f);
        }
    }
}

// Head: f[b,j] = sum_d source(j)[b, j', d];  out[b] = f[b,:] @ fcW + fcb.
__global__ void cin_final(const float* __restrict__ fcW,
                          const float* __restrict__ fcb,
                          float* __restrict__ out) {
    const int b = blockIdx.x;
    const int t = threadIdx.x;  // 256 threads

    float p = 0.0f;
    for (int j = t; j < 512; j += 256) {
        const float* src;
        if (j < 128)      src = g_y0 + (size_t)b * (HH * DD) + (size_t)j * DD;
        else if (j < 256) src = g_y1 + (size_t)b * (HH * DD) + (size_t)(j - 128) * DD;
        else              src = g_y2 + (size_t)b * (HH * DD) + (size_t)(j - 256) * DD;
        float s = 0.0f;
#pragma unroll
        for (int d = 0; d < DD; d += 4) {
            float4 v = *(const float4*)(src + d);
            s += (v.x + v.y) + (v.z + v.w);
        }
        p += s * fcW[j];
    }

    __shared__ float red[256];
    red[t] = p;
    __syncthreads();
#pragma unroll
    for (int o = 128; o > 0; o >>= 1) {
        if (t < o) red[t] += red[t + o];
        __syncthreads();
    }
    if (t == 0) out[b] = red[0] + fcb[0];
}

extern "C" void kernel_launch(void* const* d_in, const int* in_sizes, int n_in,
                              void* d_out, int out_size) {
    const float* x   = (const float*)d_in[0];
    const float* W0  = (const float*)d_in[1];
    const float* b0  = (const float*)d_in[2];
    const float* W1  = (const float*)d_in[3];
    const float* b1  = (const float*)d_in[4];
    const float* W2  = (const float*)d_in[5];
    const float* b2  = (const float*)d_in[6];
    const float* fcW = (const float*)d_in[7];
    const float* fcb = (const float*)d_in[8];
    float* out = (float*)d_out;

    cin_layer<0, 32><<<2048, 128>>>(x, W0, b0);
    cin_layer<1, 128><<<2048, 128>>>(x, W1, b1);
    cin_layer<2, 128><<<2048, 128>>>(x, W2, b2);
    cin_final<<<1024, 256>>>(fcW, fcb, out);
}

// round 4
// speedup vs baseline: 2.6632x; 2.6632x over previous
#include <cuda_runtime.h>
#include <cstdint>

#define HH 256

// Inter-layer activations + transposed tf32 weights (device scratch).
__device__ float g_y0[1024 * HH * 64];
__device__ float g_y1[1024 * HH * 64];
__device__ float g_y2[1024 * HH * 64];
__device__ float g_wt0[HH * 1024];
__device__ float g_wt1[HH * 4096];
__device__ float g_wt2[HH * 4096];

__device__ __forceinline__ uint32_t smem_u32(const void* p) {
    uint32_t r;
    asm("{ .reg .u64 t; cvta.to.shared.u64 t, %1; cvt.u32.u64 %0, t; }" : "=r"(r) : "l"(p));
    return r;
}
__device__ __forceinline__ float tf32r(float v) {
    uint32_t u;
    asm("cvt.rna.tf32.f32 %0, %1;" : "=r"(u) : "f"(v));
    return __uint_as_float(u);
}
__device__ __forceinline__ void cp16(uint32_t dst, const void* src) {
    asm volatile("cp.async.cg.shared.global [%0], [%1], 16;" :: "r"(dst), "l"(src) : "memory");
}
__device__ __forceinline__ void cp_commit() { asm volatile("cp.async.commit_group;" ::: "memory"); }
__device__ __forceinline__ void cp_wait0()  { asm volatile("cp.async.wait_group 0;" ::: "memory"); }

// ldmatrix x4: four 8x4-b32 (=8 rows x 16B) tiles; lane L supplies row L%8 of tile L/8.
__device__ __forceinline__ void ldsm4(uint32_t* r, uint32_t a) {
    asm volatile("ldmatrix.sync.aligned.m8n8.x4.shared.b16 {%0,%1,%2,%3}, [%4];"
                 : "=r"(r[0]), "=r"(r[1]), "=r"(r[2]), "=r"(r[3]) : "r"(a));
}
__device__ __forceinline__ void mma8(float* c, const uint32_t* a, const uint32_t* b) {
    asm volatile("mma.sync.aligned.m16n8k8.row.col.f32.tf32.tf32.f32 "
                 "{%0,%1,%2,%3},{%4,%5,%6,%7},{%8,%9},{%0,%1,%2,%3};"
                 : "+f"(c[0]), "+f"(c[1]), "+f"(c[2]), "+f"(c[3])
                 : "r"(a[0]), "r"(a[1]), "r"(a[2]), "r"(a[3]), "r"(b[0]), "r"(b[1]));
}

// Transpose + tf32-round: Wt[h][n*32+m] = rna(W[m*NIN+n][h]).
template <int NIN>
__global__ void wtrans(const float* __restrict__ W, float* __restrict__ Wt) {
    int k = blockIdx.x;       // 0..32*NIN-1
    int h = threadIdx.x;      // 0..255
    int m = k / NIN, n = k % NIN;
    Wt[(size_t)h * (32 * NIN) + n * 32 + m] = tf32r(W[(size_t)k * 256 + h]);
}

// One CIN layer via mma.sync tf32.
// Grid: 512 CTAs (2 batches each) x 256 threads (8 warps, 2x4 warp grid, warp tile 64x64).
// SMEM stage (48KB): A[128 rows][32 k] at 0, B=Wt[256 h][32 k] at 16384; rows = 128B,
// 16B-chunk XOR swizzle (chunk' = chunk ^ (row&7)); 2 stages double-buffered.
template <int L>
__global__ void __launch_bounds__(256, 1)
cin_layer(const float* __restrict__ x, const float* __restrict__ bias) {
    constexpr int NIN = (L == 0) ? 32 : 128;
    constexpr int K   = 32 * NIN;
    constexpr int NC  = NIN;   // chunk c covers k' = c*32..c*32+31 (n = c, m = 0..31)
    const float* wt   = (L == 0) ? g_wt0 : (L == 1) ? g_wt1 : g_wt2;
    const float* hbas = (L == 0) ? x     : (L == 1) ? g_y0 + 128 * 64 : g_y1 + 128 * 64;
    const int hstr    = (L == 0) ? 32 * 64 : HH * 64;
    float* yout       = (L == 0) ? g_y0  : (L == 1) ? g_y1 : g_y2;

    extern __shared__ char smc[];
    const uint32_t sb = smem_u32(smc);

    const int t = threadIdx.x, lane = t & 31, wid = t >> 5;
    const int b0 = blockIdx.x * 2;

    // ---- producer role: thread t owns A row prow, half phalf (4 x 16B chunks) ----
    const int prow  = t >> 1;          // 0..127  (= bb*64 + d)
    const int pbb   = prow >> 6, pd = prow & 63;
    const int phalf = t & 1;           // chunks 4*phalf .. 4*phalf+3  (m = 16*phalf..+15)
    float xr[16];
    const float* xp = x + (size_t)(b0 + pbb) * 2048 + pd;
#pragma unroll
    for (int i = 0; i < 16; i++) xr[i] = xp[(phalf * 16 + i) * 64];
    const float* hp = hbas + (size_t)(b0 + pbb) * hstr + pd;
    const uint32_t asw   = (uint32_t)(prow & 7);
    char* const    aptr  = smc + (uint32_t)prow * 128u;

    // ---- consumer role: warp (mg,ng), tile 64(d) x 64(h) ----
    const int mg = wid >> 2, ng = wid & 3;
    const int g = lane >> 3, r = lane & 7;
    // A frag (mt,ks): tile g -> rows +8*(g&1), chunk 2ks+(g>>1)
    const int arow = mg * 64 + (g & 1) * 8 + r;     // + 16*mt
    // B frag (ntile-pair np,ks): tile g -> rows +8*(g>>1), chunk 2ks+(g&1)
    const int brow = ng * 64 + (g >> 1) * 8 + r;    // + 16*np
    const uint32_t axor = (uint32_t)(arow & 7);
    const uint32_t bxor = (uint32_t)(brow & 7);
    const uint32_t aoff = sb + (uint32_t)arow * 128u;
    const uint32_t boff = sb + 16384u + (uint32_t)brow * 128u;
    const uint32_t acs = (uint32_t)(g >> 1);
    const uint32_t bcs = (uint32_t)(g & 1);

    float acc[4][8][4];
#pragma unroll
    for (int i = 0; i < 4; i++)
#pragma unroll
        for (int j = 0; j < 8; j++)
#pragma unroll
            for (int q = 0; q < 4; q++) acc[i][j][q] = 0.0f;

    auto produce = [&](int cc) {
        const uint32_t so = (uint32_t)(cc & 1) * 49152u;
        // B: Wt rows for this chunk, 2048 x 16B, 8 per thread.
        const float* ws = wt + (size_t)cc * 32;
#pragma unroll
        for (int i = 0; i < 8; i++) {
            int p = t + i * 256;
            int h = p >> 3, j = p & 7;
            cp16(sb + so + 16384u + (uint32_t)h * 128u + (uint32_t)((j ^ (h & 7)) << 4),
                 ws + (size_t)h * K + j * 4);
        }
        cp_commit();
        // A: Z[row][m] = x[b, m, d] * hprev[b, n=cc, d], tf32-rounded.
        float hv = hp[(size_t)cc * 64];
        char* ab = aptr + so;
#pragma unroll
        for (int u = 0; u < 4; u++) {
            float4 v;
            v.x = tf32r(xr[4 * u + 0] * hv);
            v.y = tf32r(xr[4 * u + 1] * hv);
            v.z = tf32r(xr[4 * u + 2] * hv);
            v.w = tf32r(xr[4 * u + 3] * hv);
            *reinterpret_cast<float4*>(ab + ((((uint32_t)(4 * phalf + u)) ^ asw) << 4)) = v;
        }
    };

    produce(0);

    for (int c = 0; c < NC; c++) {
        cp_wait0();
        __syncthreads();
        if (c + 1 < NC) produce(c + 1);

        const uint32_t so = (uint32_t)(c & 1) * 49152u;
#pragma unroll
        for (int ks = 0; ks < 4; ks++) {
            uint32_t af[4][4], bf[4][4];
#pragma unroll
            for (int mt = 0; mt < 4; mt++)
                ldsm4(af[mt], aoff + so + (uint32_t)(mt * 16 * 128) +
                              ((((uint32_t)(2 * ks) + acs) ^ axor) << 4));
#pragma unroll
            for (int np = 0; np < 4; np++)
                ldsm4(bf[np], boff + so + (uint32_t)(np * 16 * 128) +
                              ((((uint32_t)(2 * ks) + bcs) ^ bxor) << 4));
#pragma unroll
            for (int mt = 0; mt < 4; mt++)
#pragma unroll
                for (int nt = 0; nt < 8; nt++)
                    mma8(acc[mt][nt], af[mt], &bf[nt >> 1][(nt & 1) * 2]);
        }
    }

    // Epilogue: bias + relu -> y[b][h][d].
    float* yo = yout + (size_t)(b0 + mg) * (HH * 64);
    const int dq = lane >> 2, hq = (lane & 3) * 2;
#pragma unroll
    for (int mt = 0; mt < 4; mt++) {
        int d = mt * 16 + dq;
#pragma unroll
        for (int nt = 0; nt < 8; nt++) {
            int h = ng * 64 + nt * 8 + hq;
            float bv0 = __ldg(bias + h), bv1 = __ldg(bias + h + 1);
            yo[(size_t)h * 64 + d]           = fmaxf(acc[mt][nt][0] + bv0, 0.f);
            yo[(size_t)(h + 1) * 64 + d]     = fmaxf(acc[mt][nt][1] + bv1, 0.f);
            yo[(size_t)h * 64 + d + 8]       = fmaxf(acc[mt][nt][2] + bv0, 0.f);
            yo[(size_t)(h + 1) * 64 + d + 8] = fmaxf(acc[mt][nt][3] + bv1, 0.f);
        }
    }
}

// Head: f[b,j] = sum_d y; out[b] = f @ fcW + fcb.
__global__ void cin_final(const float* __restrict__ fcW,
                          const float* __restrict__ fcb,
                          float* __restrict__ out) {
    const int b = blockIdx.x;
    const int t = threadIdx.x;
    float p = 0.0f;
    for (int j = t; j < 512; j += 256) {
        const float* src;
        if (j < 128)      src = g_y0 + (size_t)b * 16384 + (size_t)j * 64;
        else if (j < 256) src = g_y1 + (size_t)b * 16384 + (size_t)(j - 128) * 64;
        else              src = g_y2 + (size_t)b * 16384 + (size_t)(j - 256) * 64;
        float s = 0.0f;
#pragma unroll
        for (int d = 0; d < 64; d += 4) {
            float4 v = *(const float4*)(src + d);
            s += (v.x + v.y) + (v.z + v.w);
        }
        p += s * fcW[j];
    }
    __shared__ float red[256];
    red[t] = p;
    __syncthreads();
#pragma unroll
    for (int o = 128; o > 0; o >>= 1) {
        if (t < o) red[t] += red[t + o];
        __syncthreads();
    }
    if (t == 0) out[b] = red[0] + fcb[0];
}

extern "C" void kernel_launch(void* const* d_in, const int* in_sizes, int n_in,
                              void* d_out, int out_size) {
    const float* x   = (const float*)d_in[0];
    const float* W0  = (const float*)d_in[1];
    const float* b0  = (const float*)d_in[2];
    const float* W1  = (const float*)d_in[3];
    const float* b1  = (const float*)d_in[4];
    const float* W2  = (const float*)d_in[5];
    const float* b2  = (const float*)d_in[6];
    const float* fcW = (const float*)d_in[7];
    const float* fcb = (const float*)d_in[8];
    float* out = (float*)d_out;

    constexpr int SMEMSZ = 2 * 49152;
    cudaFuncSetAttribute(cin_layer<0>, cudaFuncAttributeMaxDynamicSharedMemorySize, SMEMSZ);
    cudaFuncSetAttribute(cin_layer<1>, cudaFuncAttributeMaxDynamicSharedMemorySize, SMEMSZ);
    cudaFuncSetAttribute(cin_layer<2>, cudaFuncAttributeMaxDynamicSharedMemorySize, SMEMSZ);

    float *wt0p, *wt1p, *wt2p;
    cudaGetSymbolAddress((void**)&wt0p, g_wt0);
    cudaGetSymbolAddress((void**)&wt1p, g_wt1);
    cudaGetSymbolAddress((void**)&wt2p, g_wt2);

    wtrans<32>  <<<1024, 256>>>(W0, wt0p);
    wtrans<128> <<<4096, 256>>>(W1, wt1p);
    wtrans<128> <<<4096, 256>>>(W2, wt2p);

    cin_layer<0><<<512, 256, SMEMSZ>>>(x, b0);
    cin_layer<1><<<512, 256, SMEMSZ>>>(x, b1);
    cin_layer<2><<<512, 256, SMEMSZ>>>(x, b2);

    cin_final<<<1024, 256>>>(fcW, fcb, out);
}

// round 5
// speedup vs baseline: 5.4925x; 2.0624x over previous
#include <cuda_runtime.h>
#include <cuda_fp16.h>
#include <cstdint>

// ---------------- device scratch (no allocations allowed) ----------------
// Only h>=128 rows of layers 0/1 are needed downstream (as next-layer hprev).
__device__ float  g_h0[1024 * 128 * 64];
__device__ float  g_h1[1024 * 128 * 64];
// Transposed fp16 weights, chunk-tiled: Wt[c][h][kk], kk=0..63, k' = c*64+kk,
// with m = kk&31, n = 2c + (kk>>5), original k = m*NIN + n.
__device__ __half g_wt0[256 * 1024];
__device__ __half g_wt1[256 * 4096];
__device__ __half g_wt2[256 * 4096];

__device__ __forceinline__ uint32_t smem_u32(const void* p) {
    uint32_t r;
    asm("{ .reg .u64 t; cvta.to.shared.u64 t, %1; cvt.u32.u64 %0, t; }" : "=r"(r) : "l"(p));
    return r;
}
__device__ __forceinline__ uint32_t h2u(__half2 v) { return *reinterpret_cast<uint32_t*>(&v); }
__device__ __forceinline__ void cp16(uint32_t dst, const void* src) {
    asm volatile("cp.async.cg.shared.global [%0], [%1], 16;" :: "r"(dst), "l"(src) : "memory");
}
__device__ __forceinline__ void cp_commit() { asm volatile("cp.async.commit_group;" ::: "memory"); }
template <int N>
__device__ __forceinline__ void cp_wait() { asm volatile("cp.async.wait_group %0;" :: "n"(N) : "memory"); }

__device__ __forceinline__ void ldsm4(uint32_t* r, uint32_t a) {
    asm volatile("ldmatrix.sync.aligned.m8n8.x4.shared.b16 {%0,%1,%2,%3}, [%4];"
                 : "=r"(r[0]), "=r"(r[1]), "=r"(r[2]), "=r"(r[3]) : "r"(a));
}
__device__ __forceinline__ void mma16(float* c, const uint32_t* a, const uint32_t* b) {
    asm volatile("mma.sync.aligned.m16n8k16.row.col.f32.f16.f16.f32 "
                 "{%0,%1,%2,%3},{%4,%5,%6,%7},{%8,%9},{%0,%1,%2,%3};"
                 : "+f"(c[0]), "+f"(c[1]), "+f"(c[2]), "+f"(c[3])
                 : "r"(a[0]), "r"(a[1]), "r"(a[2]), "r"(a[3]), "r"(b[0]), "r"(b[1]));
}

// ---------------- weight transpose (fp16, chunk-tiled, coalesced) ----------------
// Block c handles chunk c: 64 k' x 256 h. Coalesced global reads, vector writes.
template <int NIN>
__global__ void __launch_bounds__(256) wtrans(const float* __restrict__ W, __half* __restrict__ Wt) {
    __shared__ __half s[64 * 256];
    const int c = blockIdx.x, t = threadIdx.x;
#pragma unroll 4
    for (int kk = 0; kk < 64; kk++) {
        int m = kk & 31, n = 2 * c + (kk >> 5);
        int k = m * NIN + n;
        s[kk * 256 + t] = __float2half_rn(W[(size_t)k * 256 + t]);
    }
    __syncthreads();
    __half* dst = Wt + (size_t)c * 16384 + (size_t)t * 64;   // row h = t, 64 halfs
#pragma unroll
    for (int j = 0; j < 8; j++) {
        uint4 v;
        v.x = h2u(__halves2half2(s[(8 * j + 0) * 256 + t], s[(8 * j + 1) * 256 + t]));
        v.y = h2u(__halves2half2(s[(8 * j + 2) * 256 + t], s[(8 * j + 3) * 256 + t]));
        v.z = h2u(__halves2half2(s[(8 * j + 4) * 256 + t], s[(8 * j + 5) * 256 + t]));
        v.w = h2u(__halves2half2(s[(8 * j + 6) * 256 + t], s[(8 * j + 7) * 256 + t]));
        *reinterpret_cast<uint4*>(dst + 8 * j) = v;
    }
}

__global__ void init_out(const float* __restrict__ fcb, float* __restrict__ out) {
    out[blockIdx.x * 256 + threadIdx.x] = fcb[0];
}

// ---------------- CIN layer: fp16 mma.sync, fused head dot ----------------
// 512 CTAs (2 batches each) x 256 threads (8 warps, 2x4, warp tile 64d x 64h).
// K-chunk = 64 (two n). Stage (48KB): A[128 rows x 128B] @0, B[256 rows x 128B] @16384.
// 3 stages. Rows SW-swizzled per 16B chunk: chunk' = chunk ^ (row & 7).
template <int L>
__global__ void __launch_bounds__(256, 1)
cin_layer(const float* __restrict__ x, const float* __restrict__ bias,
          const float* __restrict__ fcW, float* __restrict__ out) {
    constexpr int NIN = (L == 0) ? 32 : 128;
    constexpr int NC  = NIN / 2;                 // chunks of 64 k'
    const __half* wt  = (L == 0) ? g_wt0 : (L == 1) ? g_wt1 : g_wt2;
    const float* hbas = (L == 0) ? x : (L == 1) ? g_h0 : g_h1;
    const int hstr    = (L == 0) ? 2048 : 8192;

    extern __shared__ char smc[];
    const uint32_t sb = smem_u32(smc);

    const int t = threadIdx.x, lane = t & 31, wid = t >> 5;
    const int b0 = blockIdx.x * 2;

    // ---- producer: thread owns A row (t>>1), n-half (t&1): one n, 32 m ----
    const int prow = t >> 1, pbb = prow >> 6, pd = prow & 63;
    const int nhalf = t & 1;
    float xr[32];
    const float* xp = x + (size_t)(b0 + pbb) * 2048 + pd;
#pragma unroll
    for (int m = 0; m < 32; m++) xr[m] = xp[m * 64];
    const float* hp = hbas + (size_t)(b0 + pbb) * hstr + pd;
    const uint32_t asw = (uint32_t)(prow & 7);
    char* const aptr = smc + (uint32_t)prow * 128u;

    // ---- consumer: warp (mg,ng) ----
    const int mg = wid >> 2, ng = wid & 3;
    const int arow = mg * 64 + (lane & 15);                       // + 16*mt
    const int brow = ng * 64 + ((lane >> 4) << 3) + (lane & 7);   // + 16*np
    const uint32_t axor = (uint32_t)(arow & 7);
    const uint32_t bxor = (uint32_t)(brow & 7);
    const uint32_t aoff = sb + (uint32_t)arow * 128u;
    const uint32_t boff = sb + 16384u + (uint32_t)brow * 128u;
    const uint32_t acs = (uint32_t)(lane >> 4);
    const uint32_t bcs = (uint32_t)((lane >> 3) & 1);

    float acc[4][8][4];
#pragma unroll
    for (int i = 0; i < 4; i++)
#pragma unroll
        for (int j = 0; j < 8; j++)
#pragma unroll
            for (int q = 0; q < 4; q++) acc[i][j][q] = 0.0f;

    auto produce = [&](int cc) {
        const uint32_t so = (uint32_t)(cc % 3) * 49152u;
        // B: 256 rows x 128B, 2048 x 16B chunks, 8 per thread (cp.async).
        const __half* ws = wt + (size_t)cc * 16384;
#pragma unroll
        for (int i = 0; i < 8; i++) {
            int p = t + i * 256;
            int h = p >> 3, j = p & 7;
            cp16(sb + so + 16384u + (uint32_t)h * 128u + (uint32_t)((j ^ (h & 7)) << 4),
                 ws + (size_t)h * 64 + j * 8);
        }
        cp_commit();
        // A: Z[row][kk] = fp16(x[m]*h[n]), kk = nhalf*32 + m.
        float hv = hp[(size_t)(2 * cc + nhalf) * 64];
        char* ab = aptr + so;
#pragma unroll
        for (int u = 0; u < 4; u++) {
            uint4 v;
            v.x = h2u(__floats2half2_rn(xr[8 * u + 0] * hv, xr[8 * u + 1] * hv));
            v.y = h2u(__floats2half2_rn(xr[8 * u + 2] * hv, xr[8 * u + 3] * hv));
            v.z = h2u(__floats2half2_rn(xr[8 * u + 4] * hv, xr[8 * u + 5] * hv));
            v.w = h2u(__floats2half2_rn(xr[8 * u + 6] * hv, xr[8 * u + 7] * hv));
            *reinterpret_cast<uint4*>(ab + ((((uint32_t)(4 * nhalf + u)) ^ asw) << 4)) = v;
        }
    };

    produce(0);
    produce(1);

    for (int c = 0; c < NC; c++) {
        if (c + 1 < NC) cp_wait<1>(); else cp_wait<0>();
        __syncthreads();
        if (c + 2 < NC) produce(c + 2);

        const uint32_t so = (uint32_t)(c % 3) * 49152u;
#pragma unroll
        for (int ks = 0; ks < 4; ks++) {
            uint32_t af[4][4], bf[4][4];
#pragma unroll
            for (int mt = 0; mt < 4; mt++)
                ldsm4(af[mt], aoff + so + (uint32_t)(mt * 16 * 128) +
                              ((((uint32_t)(2 * ks) + acs) ^ axor) << 4));
#pragma unroll
            for (int np = 0; np < 4; np++)
                ldsm4(bf[np], boff + so + (uint32_t)(np * 16 * 128) +
                              ((((uint32_t)(2 * ks) + bcs) ^ bxor) << 4));
#pragma unroll
            for (int mt = 0; mt < 4; mt++)
#pragma unroll
                for (int nt = 0; nt < 8; nt++)
                    mma16(acc[mt][nt], af[mt], &bf[nt >> 1][(nt & 1) * 2]);
        }
    }

    // ---- epilogue: bias+relu; h<128 (L<2) / all h (L==2) -> fused fc dot;
    //      h>=128 (L<2) -> write as next layer's hprev. ----
    const int b = b0 + mg;
    const int dq = lane >> 2, hq = (lane & 3) * 2;
    if (L == 2 || ng < 2) {
        float p = 0.0f;
#pragma unroll
        for (int nt = 0; nt < 8; nt++) {
            int h = ng * 64 + nt * 8 + hq;
            float bv0 = __ldg(bias + h), bv1 = __ldg(bias + h + 1);
            int j = (L == 0) ? h : (L == 1) ? 128 + h : 256 + h;
            float w0 = __ldg(fcW + j), w1 = __ldg(fcW + j + 1);
            float s0 = 0.0f, s1 = 0.0f;
#pragma unroll
            for (int mt = 0; mt < 4; mt++) {
                s0 += fmaxf(acc[mt][nt][0] + bv0, 0.f) + fmaxf(acc[mt][nt][2] + bv0, 0.f);
                s1 += fmaxf(acc[mt][nt][1] + bv1, 0.f) + fmaxf(acc[mt][nt][3] + bv1, 0.f);
            }
            p += s0 * w0 + s1 * w1;
        }
#pragma unroll
        for (int o = 16; o > 0; o >>= 1) p += __shfl_xor_sync(0xFFFFFFFFu, p, o);
        if (lane == 0) atomicAdd(out + b, p);
    }
    if (L < 2 && ng >= 2) {
        float* yo = (L == 0 ? g_h0 : g_h1) + (size_t)b * 8192;
#pragma unroll
        for (int mt = 0; mt < 4; mt++) {
            int d = mt * 16 + dq;
#pragma unroll
            for (int nt = 0; nt < 8; nt++) {
                int h = ng * 64 + nt * 8 + hq;
                float bv0 = __ldg(bias + h), bv1 = __ldg(bias + h + 1);
                int n = h - 128;
                yo[(size_t)n * 64 + d]           = fmaxf(acc[mt][nt][0] + bv0, 0.f);
                yo[(size_t)(n + 1) * 64 + d]     = fmaxf(acc[mt][nt][1] + bv1, 0.f);
                yo[(size_t)n * 64 + d + 8]       = fmaxf(acc[mt][nt][2] + bv0, 0.f);
                yo[(size_t)(n + 1) * 64 + d + 8] = fmaxf(acc[mt][nt][3] + bv1, 0.f);
            }
        }
    }
}

extern "C" void kernel_launch(void* const* d_in, const int* in_sizes, int n_in,
                              void* d_out, int out_size) {
    const float* x   = (const float*)d_in[0];
    const float* W0  = (const float*)d_in[1];
    const float* b0  = (const float*)d_in[2];
    const float* W1  = (const float*)d_in[3];
    const float* b1  = (const float*)d_in[4];
    const float* W2  = (const float*)d_in[5];
    const float* b2  = (const float*)d_in[6];
    const float* fcW = (const float*)d_in[7];
    const float* fcb = (const float*)d_in[8];
    float* out = (float*)d_out;

    constexpr int SMEMSZ = 3 * 49152;
    cudaFuncSetAttribute(cin_layer<0>, cudaFuncAttributeMaxDynamicSharedMemorySize, SMEMSZ);
    cudaFuncSetAttribute(cin_layer<1>, cudaFuncAttributeMaxDynamicSharedMemorySize, SMEMSZ);
    cudaFuncSetAttribute(cin_layer<2>, cudaFuncAttributeMaxDynamicSharedMemorySize, SMEMSZ);

    __half *wt0p, *wt1p, *wt2p;
    cudaGetSymbolAddress((void**)&wt0p, g_wt0);
    cudaGetSymbolAddress((void**)&wt1p, g_wt1);
    cudaGetSymbolAddress((void**)&wt2p, g_wt2);

    wtrans<32>  <<<16, 256>>>(W0, wt0p);
    wtrans<128> <<<64, 256>>>(W1, wt1p);
    wtrans<128> <<<64, 256>>>(W2, wt2p);
    init_out<<<4, 256>>>(fcb, out);

    cin_layer<0><<<512, 256, SMEMSZ>>>(x, b0, fcW, out);
    cin_layer<1><<<512, 256, SMEMSZ>>>(x, b1, fcW, out);
    cin_layer<2><<<512, 256, SMEMSZ>>>(x, b2, fcW, out);
}

// round 6
// speedup vs baseline: 5.5843x; 1.0167x over previous
#include <cuda_runtime.h>
#include <cuda_fp16.h>
#include <cstdint>

// ---------------- device scratch (no allocations allowed) ----------------
// Only h>=128 rows of layers 0/1 are needed downstream (as next-layer hprev).
__device__ float  g_h0[1024 * 128 * 64];
__device__ float  g_h1[1024 * 128 * 64];
// Transposed fp16 weights, chunk-tiled (chunk = 128 k'):
// Wt[c][h][kk], kk = nl*32 + m (nl=0..3), n = 4c + nl, original k = m*NIN + n.
__device__ __half g_wt0[256 * 1024];
__device__ __half g_wt1[256 * 4096];
__device__ __half g_wt2[256 * 4096];

__device__ __forceinline__ uint32_t smem_u32(const void* p) {
    uint32_t r;
    asm("{ .reg .u64 t; cvta.to.shared.u64 t, %1; cvt.u32.u64 %0, t; }" : "=r"(r) : "l"(p));
    return r;
}
__device__ __forceinline__ uint32_t h2u(__half2 v) { return *reinterpret_cast<uint32_t*>(&v); }
__device__ __forceinline__ void cp16(uint32_t dst, const void* src) {
    asm volatile("cp.async.cg.shared.global [%0], [%1], 16;" :: "r"(dst), "l"(src) : "memory");
}
__device__ __forceinline__ void cp_commit() { asm volatile("cp.async.commit_group;" ::: "memory"); }
template <int N>
__device__ __forceinline__ void cp_wait() { asm volatile("cp.async.wait_group %0;" :: "n"(N) : "memory"); }

__device__ __forceinline__ void ldsm4(uint32_t* r, uint32_t a) {
    asm volatile("ldmatrix.sync.aligned.m8n8.x4.shared.b16 {%0,%1,%2,%3}, [%4];"
                 : "=r"(r[0]), "=r"(r[1]), "=r"(r[2]), "=r"(r[3]) : "r"(a));
}
__device__ __forceinline__ void mma16(float* c, const uint32_t* a, const uint32_t* b) {
    asm volatile("mma.sync.aligned.m16n8k16.row.col.f32.f16.f16.f32 "
                 "{%0,%1,%2,%3},{%4,%5,%6,%7},{%8,%9},{%0,%1,%2,%3};"
                 : "+f"(c[0]), "+f"(c[1]), "+f"(c[2]), "+f"(c[3])
                 : "r"(a[0]), "r"(a[1]), "r"(a[2]), "r"(a[3]), "r"(b[0]), "r"(b[1]));
}

// ---------------- weight transpose (fp16, chunk-128 tiling, coalesced) ----------------
// Block b2: chunk c = b2>>1, half hh = b2&1 (kk = hh*64 + nl2*32 + m, nl = 2*hh + nl2).
template <int NIN>
__global__ void __launch_bounds__(256) wtrans(const float* __restrict__ W, __half* __restrict__ Wt) {
    __shared__ __half s[64 * 256];
    const int c = blockIdx.x >> 1, hh = blockIdx.x & 1, t = threadIdx.x;
#pragma unroll 4
    for (int kk2 = 0; kk2 < 64; kk2++) {
        int m = kk2 & 31, nl2 = kk2 >> 5;
        int n = 4 * c + 2 * hh + nl2;
        int k = m * NIN + n;
        s[kk2 * 256 + t] = __float2half_rn(W[(size_t)k * 256 + t]);
    }
    __syncthreads();
    __half* dst = Wt + (size_t)c * 32768 + (size_t)t * 128 + hh * 64;
#pragma unroll
    for (int j = 0; j < 8; j++) {
        uint4 v;
        v.x = h2u(__halves2half2(s[(8 * j + 0) * 256 + t], s[(8 * j + 1) * 256 + t]));
        v.y = h2u(__halves2half2(s[(8 * j + 2) * 256 + t], s[(8 * j + 3) * 256 + t]));
        v.z = h2u(__halves2half2(s[(8 * j + 4) * 256 + t], s[(8 * j + 5) * 256 + t]));
        v.w = h2u(__halves2half2(s[(8 * j + 6) * 256 + t], s[(8 * j + 7) * 256 + t]));
        *reinterpret_cast<uint4*>(dst + 8 * j) = v;
    }
}

__global__ void init_out(const float* __restrict__ fcb, float* __restrict__ out) {
    out[blockIdx.x * 256 + threadIdx.x] = fcb[0];
}

// ---------------- CIN layer: fp16 mma.sync, K-chunk 128, fused head dot ----------------
// 512 CTAs (2 batches each) x 256 threads (8 warps, 2x4, warp tile 64d x 64h).
// Stage (96KB): A[128 rows x 256B] @0, B[256 rows x 256B] @32768; 2 stages.
// Rows swizzled per 16B chunk: chunk' = chunk ^ (row & 7) (low 3 bits of 4-bit index).
template <int L>
__global__ void __launch_bounds__(256, 1)
cin_layer(const float* __restrict__ x, const float* __restrict__ bias,
          const float* __restrict__ fcW, float* __restrict__ out) {
    constexpr int NIN = (L == 0) ? 32 : 128;
    constexpr int NC  = NIN / 4;                 // chunks of 128 k' (4 n each)
    const __half* wt  = (L == 0) ? g_wt0 : (L == 1) ? g_wt1 : g_wt2;
    const float* hbas = (L == 0) ? x : (L == 1) ? g_h0 : g_h1;
    const int hstr    = (L == 0) ? 2048 : 8192;

    extern __shared__ char smc[];
    const uint32_t sb = smem_u32(smc);

    const int t = threadIdx.x, lane = t & 31, wid = t >> 5;
    const int b0 = blockIdx.x * 2;

    // ---- producer: thread owns A row (t>>1); k-half (t&1): 2 n's x 32 m ----
    const int prow = t >> 1, pbb = prow >> 6, pd = prow & 63;
    const int nhalf = t & 1;
    float xr[32];
    const float* xp = x + (size_t)(b0 + pbb) * 2048 + pd;
#pragma unroll
    for (int m = 0; m < 32; m++) xr[m] = xp[m * 64];
    const float* hp = hbas + (size_t)(b0 + pbb) * hstr + pd;
    const uint32_t asw = (uint32_t)(prow & 7);
    char* const aptr = smc + (uint32_t)prow * 256u;

    // ---- consumer: warp (mg,ng), tile 64d x 64h ----
    const int mg = wid >> 2, ng = wid & 3;
    const int arow = mg * 64 + (lane & 15);                       // + 16*mt
    const int brow = ng * 64 + ((lane >> 4) << 3) + (lane & 7);   // + 16*np
    const uint32_t axor = (uint32_t)(arow & 7);
    const uint32_t bxor = (uint32_t)(brow & 7);
    const uint32_t aoff = sb + (uint32_t)arow * 256u;
    const uint32_t boff = sb + 32768u + (uint32_t)brow * 256u;
    const uint32_t acs = (uint32_t)(lane >> 4);
    const uint32_t bcs = (uint32_t)((lane >> 3) & 1);

    float acc[4][8][4];
#pragma unroll
    for (int i = 0; i < 4; i++)
#pragma unroll
        for (int j = 0; j < 8; j++)
#pragma unroll
            for (int q = 0; q < 4; q++) acc[i][j][q] = 0.0f;

    auto produce = [&](int cc) {
        const uint32_t so = (uint32_t)(cc & 1) * 98304u;
        // B: 256 rows x 256B = 4096 x 16B chunks, 16 per thread (cp.async).
        const __half* ws = wt + (size_t)cc * 32768;
#pragma unroll
        for (int i = 0; i < 16; i++) {
            int p = t + i * 256;
            int h = p >> 4, j = p & 15;
            cp16(sb + so + 32768u + (uint32_t)h * 256u + (uint32_t)((j ^ (h & 7)) << 4),
                 ws + (size_t)h * 128 + j * 8);
        }
        cp_commit();
        // A: Z[row][kk] = fp16(x[m]*h[n]), kk = nl*32 + m, nl = 2*nhalf + nl2.
        char* ab = aptr + so;
#pragma unroll
        for (int nl2 = 0; nl2 < 2; nl2++) {
            float hv = hp[(size_t)(4 * cc + 2 * nhalf + nl2) * 64];
#pragma unroll
            for (int u = 0; u < 4; u++) {
                uint4 v;
                v.x = h2u(__floats2half2_rn(xr[8 * u + 0] * hv, xr[8 * u + 1] * hv));
                v.y = h2u(__floats2half2_rn(xr[8 * u + 2] * hv, xr[8 * u + 3] * hv));
                v.z = h2u(__floats2half2_rn(xr[8 * u + 4] * hv, xr[8 * u + 5] * hv));
                v.w = h2u(__floats2half2_rn(xr[8 * u + 6] * hv, xr[8 * u + 7] * hv));
                int j = nhalf * 8 + nl2 * 4 + u;
                *reinterpret_cast<uint4*>(ab + ((((uint32_t)j) ^ asw) << 4)) = v;
            }
        }
    };

    produce(0);

    for (int c = 0; c < NC; c++) {
        cp_wait<0>();
        __syncthreads();
        if (c + 1 < NC) produce(c + 1);

        const uint32_t so = (uint32_t)(c & 1) * 98304u;
#pragma unroll
        for (int ks = 0; ks < 8; ks++) {
            uint32_t af[4][4], bf[4][4];
#pragma unroll
            for (int mt = 0; mt < 4; mt++)
                ldsm4(af[mt], aoff + so + (uint32_t)(mt * 16 * 256) +
                              ((((uint32_t)(2 * ks) + acs) ^ axor) << 4));
#pragma unroll
            for (int np = 0; np < 4; np++)
                ldsm4(bf[np], boff + so + (uint32_t)(np * 16 * 256) +
                              ((((uint32_t)(2 * ks) + bcs) ^ bxor) << 4));
#pragma unroll
            for (int mt = 0; mt < 4; mt++)
#pragma unroll
                for (int nt = 0; nt < 8; nt++)
                    mma16(acc[mt][nt], af[mt], &bf[nt >> 1][(nt & 1) * 2]);
        }
        __syncthreads();
    }

    // ---- epilogue: bias+relu; h<128 (L<2) / all h (L==2) -> fused fc dot;
    //      h>=128 (L<2) -> write as next layer's hprev. ----
    const int b = b0 + mg;
    const int dq = lane >> 2, hq = (lane & 3) * 2;
    if (L == 2 || ng < 2) {
        float p = 0.0f;
#pragma unroll
        for (int nt = 0; nt < 8; nt++) {
            int h = ng * 64 + nt * 8 + hq;
            float bv0 = __ldg(bias + h), bv1 = __ldg(bias + h + 1);
            int j = (L == 0) ? h : (L == 1) ? 128 + h : 256 + h;
            float w0 = __ldg(fcW + j), w1 = __ldg(fcW + j + 1);
            float s0 = 0.0f, s1 = 0.0f;
#pragma unroll
            for (int mt = 0; mt < 4; mt++) {
                s0 += fmaxf(acc[mt][nt][0] + bv0, 0.f) + fmaxf(acc[mt][nt][2] + bv0, 0.f);
                s1 += fmaxf(acc[mt][nt][1] + bv1, 0.f) + fmaxf(acc[mt][nt][3] + bv1, 0.f);
            }
            p += s0 * w0 + s1 * w1;
        }
#pragma unroll
        for (int o = 16; o > 0; o >>= 1) p += __shfl_xor_sync(0xFFFFFFFFu, p, o);
        if (lane == 0) atomicAdd(out + b, p);
    }
    if (L < 2 && ng >= 2) {
        float* yo = (L == 0 ? g_h0 : g_h1) + (size_t)b * 8192;
#pragma unroll
        for (int mt = 0; mt < 4; mt++) {
            int d = mt * 16 + dq;
#pragma unroll
            for (int nt = 0; nt < 8; nt++) {
                int h = ng * 64 + nt * 8 + hq;
                float bv0 = __ldg(bias + h), bv1 = __ldg(bias + h + 1);
                int n = h - 128;
                yo[(size_t)n * 64 + d]           = fmaxf(acc[mt][nt][0] + bv0, 0.f);
                yo[(size_t)(n + 1) * 64 + d]     = fmaxf(acc[mt][nt][1] + bv1, 0.f);
                yo[(size_t)n * 64 + d + 8]       = fmaxf(acc[mt][nt][2] + bv0, 0.f);
                yo[(size_t)(n + 1) * 64 + d + 8] = fmaxf(acc[mt][nt][3] + bv1, 0.f);
            }
        }
    }
}

extern "C" void kernel_launch(void* const* d_in, const int* in_sizes, int n_in,
                              void* d_out, int out_size) {
    const float* x   = (const float*)d_in[0];
    const float* W0  = (const float*)d_in[1];
    const float* b0  = (const float*)d_in[2];
    const float* W1  = (const float*)d_in[3];
    const float* b1  = (const float*)d_in[4];
    const float* W2  = (const float*)d_in[5];
    const float* b2  = (const float*)d_in[6];
    const float* fcW = (const float*)d_in[7];
    const float* fcb = (const float*)d_in[8];
    float* out = (float*)d_out;

    constexpr int SMEMSZ = 2 * 98304;   // 192 KB
    cudaFuncSetAttribute(cin_layer<0>, cudaFuncAttributeMaxDynamicSharedMemorySize, SMEMSZ);
    cudaFuncSetAttribute(cin_layer<1>, cudaFuncAttributeMaxDynamicSharedMemorySize, SMEMSZ);
    cudaFuncSetAttribute(cin_layer<2>, cudaFuncAttributeMaxDynamicSharedMemorySize, SMEMSZ);

    __half *wt0p, *wt1p, *wt2p;
    cudaGetSymbolAddress((void**)&wt0p, g_wt0);
    cudaGetSymbolAddress((void**)&wt1p, g_wt1);
    cudaGetSymbolAddress((void**)&wt2p, g_wt2);

    wtrans<32>  <<<16, 256>>>(W0, wt0p);
    wtrans<128> <<<64, 256>>>(W1, wt1p);
    wtrans<128> <<<64, 256>>>(W2, wt2p);
    init_out<<<4, 256>>>(fcb, out);

    cin_layer<0><<<512, 256, SMEMSZ>>>(x, b0, fcW, out);
    cin_layer<1><<<512, 256, SMEMSZ>>>(x, b1, fcW, out);
    cin_layer<2><<<512, 256, SMEMSZ>>>(x, b2, fcW, out);
}

// round 7
// speedup vs baseline: 6.0904x; 1.0906x over previous
#include <cuda_runtime.h>
#include <cuda_fp16.h>
#include <cstdint>

// ---------------- device scratch (no allocations allowed) ----------------
// Only h>=128 rows of layers 0/1 are needed downstream (next-layer hprev).
__device__ float  g_h0[1024 * 128 * 64];
__device__ float  g_h1[1024 * 128 * 64];
// Transposed fp16 weights, chunk-tiled (chunk = 64 k'):
// Wt[c][h][kk], kk = nl*32 + m (nl=0..1), n = 2c + nl, original k = m*NIN + n.
__device__ __half g_wt0[256 * 1024];
__device__ __half g_wt1[256 * 4096];
__device__ __half g_wt2[256 * 4096];

__device__ __forceinline__ uint32_t smem_u32(const void* p) {
    uint32_t r;
    asm("{ .reg .u64 t; cvta.to.shared.u64 t, %1; cvt.u32.u64 %0, t; }" : "=r"(r) : "l"(p));
    return r;
}
__device__ __forceinline__ uint32_t h2u(__half2 v) { return *reinterpret_cast<uint32_t*>(&v); }
__device__ __forceinline__ void cp16(uint32_t dst, const void* src) {
    asm volatile("cp.async.cg.shared.global [%0], [%1], 16;" :: "r"(dst), "l"(src) : "memory");
}
__device__ __forceinline__ void cp_mbar_arrive(uint32_t mbar) {
    asm volatile("cp.async.mbarrier.arrive.noinc.shared.b64 [%0];" :: "r"(mbar) : "memory");
}
__device__ __forceinline__ void mbar_init(uint32_t a, uint32_t c) {
    asm volatile("mbarrier.init.shared.b64 [%0], %1;" :: "r"(a), "r"(c) : "memory");
}
__device__ __forceinline__ void mbar_arrive(uint32_t a) {
    asm volatile("mbarrier.arrive.shared.b64 _, [%0];" :: "r"(a) : "memory");
}
__device__ __forceinline__ void mbar_wait(uint32_t a, uint32_t ph) {
    asm volatile(
        "{\n\t.reg .pred P;\n"
        "W_%=:\n\t"
        "mbarrier.try_wait.parity.shared.b64 P, [%0], %1, 0x989680;\n\t"
        "@P bra.uni D_%=;\n\t"
        "bra.uni W_%=;\n"
        "D_%=:\n\t}"
        :: "r"(a), "r"(ph) : "memory");
}
__device__ __forceinline__ void ldsm4(uint32_t* r, uint32_t a) {
    asm volatile("ldmatrix.sync.aligned.m8n8.x4.shared.b16 {%0,%1,%2,%3}, [%4];"
                 : "=r"(r[0]), "=r"(r[1]), "=r"(r[2]), "=r"(r[3]) : "r"(a));
}
__device__ __forceinline__ void mma16(float* c, const uint32_t* a, const uint32_t* b) {
    asm volatile("mma.sync.aligned.m16n8k16.row.col.f32.f16.f16.f32 "
                 "{%0,%1,%2,%3},{%4,%5,%6,%7},{%8,%9},{%0,%1,%2,%3};"
                 : "+f"(c[0]), "+f"(c[1]), "+f"(c[2]), "+f"(c[3])
                 : "r"(a[0]), "r"(a[1]), "r"(a[2]), "r"(a[3]), "r"(b[0]), "r"(b[1]));
}

// ---------------- weight transpose (fp16, chunk-64 tiling, coalesced) ----------------
// Block c handles chunk c: 64 k' x 256 h.
template <int NIN>
__global__ void __launch_bounds__(256) wtrans(const float* __restrict__ W, __half* __restrict__ Wt) {
    __shared__ __half s[64 * 256];
    const int c = blockIdx.x, t = threadIdx.x;
#pragma unroll 4
    for (int kk = 0; kk < 64; kk++) {
        int m = kk & 31, nl = kk >> 5;
        int n = 2 * c + nl;
        int k = m * NIN + n;
        s[kk * 256 + t] = __float2half_rn(W[(size_t)k * 256 + t]);
    }
    __syncthreads();
    __half* dst = Wt + (size_t)c * 16384 + (size_t)t * 64;   // row h = t, 64 halfs
#pragma unroll
    for (int j = 0; j < 8; j++) {
        uint4 v;
        v.x = h2u(__halves2half2(s[(8 * j + 0) * 256 + t], s[(8 * j + 1) * 256 + t]));
        v.y = h2u(__halves2half2(s[(8 * j + 2) * 256 + t], s[(8 * j + 3) * 256 + t]));
        v.z = h2u(__halves2half2(s[(8 * j + 4) * 256 + t], s[(8 * j + 5) * 256 + t]));
        v.w = h2u(__halves2half2(s[(8 * j + 6) * 256 + t], s[(8 * j + 7) * 256 + t]));
        *reinterpret_cast<uint4*>(dst + 8 * j) = v;
    }
}

__global__ void init_out(const float* __restrict__ fcb, float* __restrict__ out) {
    out[blockIdx.x * 256 + threadIdx.x] = fcb[0];
}

// ---------------- CIN layer: warp-specialized fp16 mma.sync ----------------
// 512 CTAs (2 batches each) x 320 threads:
//   warps 0-7  = consumers (2x4 warp grid, warp tile 64d x 64h)
//   warps 8-9  = producers (64 threads; thread owns A rows ptid and ptid+64)
// K-chunk 64 (2 n). Stage (48KB): A[128 x 128B] @0, B[256 x 128B] @16384.
// 4 stages + mbarrier header. Rows swizzled per 16B chunk: j' = j ^ (row & 7).
// full[s]: 128 arrivals (64 cp.async-completions + 64 A-store arrives).
// empty[s]: 256 arrivals (consumer threads).
template <int L>
__global__ void __launch_bounds__(320, 1)
cin_layer(const float* __restrict__ x, const float* __restrict__ bias,
          const float* __restrict__ fcW, float* __restrict__ out) {
    constexpr int NIN = (L == 0) ? 32 : 128;
    constexpr int NC  = NIN / 2;                 // chunks of 64 k'
    const __half* wt  = (L == 0) ? g_wt0 : (L == 1) ? g_wt1 : g_wt2;
    const float* hbas = (L == 0) ? x : (L == 1) ? g_h0 : g_h1;
    const int hstr    = (L == 0) ? 2048 : 8192;

    extern __shared__ char smc[];
    const uint32_t sb0 = smem_u32(smc);
    const uint32_t sb  = (sb0 + 1023u) & ~1023u;       // aligned base
    // header: full[s] @ sb + 16s, empty[s] @ sb + 16s + 8; stages @ sb + 1024.
    const uint32_t stg0 = sb + 1024u;

    const int t = threadIdx.x, lane = t & 31, wid = t >> 5;
    const int b0 = blockIdx.x * 2;

    if (t == 0) {
#pragma unroll
        for (int s = 0; s < 4; s++) {
            mbar_init(sb + 16 * s, 128);
            mbar_init(sb + 16 * s + 8, 256);
        }
    }
    __syncthreads();

    if (t >= 256) {
        // ================= producer =================
        const int ptid = t - 256;                       // 0..63
        float xr0[32], xr1[32];
        const float* xp0 = x + (size_t)b0 * 2048 + ptid;
        const float* xp1 = x + (size_t)(b0 + 1) * 2048 + ptid;
#pragma unroll
        for (int m = 0; m < 32; m++) { xr0[m] = xp0[m * 64]; xr1[m] = xp1[m * 64]; }
        const float* hp0 = hbas + (size_t)b0 * hstr + ptid;
        const float* hp1 = hbas + (size_t)(b0 + 1) * hstr + ptid;

        for (int c = 0; c < NC; c++) {
            const int s = c & 3;
            const uint32_t ph = 1u ^ ((uint32_t)(c >> 2) & 1u);
            mbar_wait(sb + 16 * s + 8, ph);             // stage free
            const uint32_t stg = stg0 + (uint32_t)s * 49152u;
            // B: 2048 x 16B chunks over 64 threads -> 32 cp16 each.
            const __half* ws = wt + (size_t)c * 16384;
#pragma unroll
            for (int i = 0; i < 32; i++) {
                int p = ptid + i * 64;
                int h = p >> 3, j = p & 7;
                cp16(stg + 16384u + (uint32_t)h * 128u + (uint32_t)((j ^ (h & 7)) << 4),
                     ws + (size_t)h * 64 + j * 8);
            }
            cp_mbar_arrive(sb + 16 * s);                // arrive full on cp completion
            // A: rows ptid (batch b0) and ptid+64 (batch b0+1).
#pragma unroll
            for (int r2 = 0; r2 < 2; r2++) {
                const int row = ptid + r2 * 64;
                const float* xr = r2 ? xr1 : xr0;
                const float* hp = r2 ? hp1 : hp0;
                const uint32_t asw = (uint32_t)(row & 7);
                char* ab = smc + (stg - sb0) + (uint32_t)row * 128u;
#pragma unroll
                for (int nl = 0; nl < 2; nl++) {
                    float hv = hp[(size_t)(2 * c + nl) * 64];
#pragma unroll
                    for (int u = 0; u < 4; u++) {
                        uint4 v;
                        v.x = h2u(__floats2half2_rn(xr[8 * u + 0] * hv, xr[8 * u + 1] * hv));
                        v.y = h2u(__floats2half2_rn(xr[8 * u + 2] * hv, xr[8 * u + 3] * hv));
                        v.z = h2u(__floats2half2_rn(xr[8 * u + 4] * hv, xr[8 * u + 5] * hv));
                        v.w = h2u(__floats2half2_rn(xr[8 * u + 6] * hv, xr[8 * u + 7] * hv));
                        int j = nl * 4 + u;
                        *reinterpret_cast<uint4*>(ab + ((((uint32_t)j) ^ asw) << 4)) = v;
                    }
                }
            }
            mbar_arrive(sb + 16 * s);                   // A ready (release)
        }
        return;
    }

    // ================= consumer =================
    const int mg = wid >> 2, ng = wid & 3;
    const int arow = mg * 64 + (lane & 15);                       // + 16*mt
    const int brow = ng * 64 + ((lane >> 4) << 3) + (lane & 7);   // + 16*np
    const uint32_t axor = (uint32_t)(arow & 7);
    const uint32_t bxor = (uint32_t)(brow & 7);
    const uint32_t aof = (uint32_t)arow * 128u;
    const uint32_t bof = 16384u + (uint32_t)brow * 128u;
    const uint32_t acs = (uint32_t)(lane >> 4);
    const uint32_t bcs = (uint32_t)((lane >> 3) & 1);

    float acc[4][8][4];
#pragma unroll
    for (int i = 0; i < 4; i++)
#pragma unroll
        for (int j = 0; j < 8; j++)
#pragma unroll
            for (int q = 0; q < 4; q++) acc[i][j][q] = 0.0f;

    for (int c = 0; c < NC; c++) {
        const int s = c & 3;
        const uint32_t ph = (uint32_t)(c >> 2) & 1u;
        mbar_wait(sb + 16 * s, ph);                     // stage full
        const uint32_t stg = stg0 + (uint32_t)s * 49152u;
#pragma unroll
        for (int ks = 0; ks < 4; ks++) {
            uint32_t af[4][4], bf[4][4];
#pragma unroll
            for (int mt = 0; mt < 4; mt++)
                ldsm4(af[mt], stg + aof + (uint32_t)(mt * 16 * 128) +
                              ((((uint32_t)(2 * ks) + acs) ^ axor) << 4));
#pragma unroll
            for (int np = 0; np < 4; np++)
                ldsm4(bf[np], stg + bof + (uint32_t)(np * 16 * 128) +
                              ((((uint32_t)(2 * ks) + bcs) ^ bxor) << 4));
#pragma unroll
            for (int mt = 0; mt < 4; mt++)
#pragma unroll
                for (int nt = 0; nt < 8; nt++)
                    mma16(acc[mt][nt], af[mt], &bf[nt >> 1][(nt & 1) * 2]);
        }
        mbar_arrive(sb + 16 * s + 8);                   // stage consumed
    }

    // ---- epilogue: bias+relu; h<128 (L<2) / all h (L==2) -> fused fc dot;
    //      h>=128 (L<2) -> write as next layer's hprev. ----
    const int b = b0 + mg;
    const int dq = lane >> 2, hq = (lane & 3) * 2;
    if (L == 2 || ng < 2) {
        float p = 0.0f;
#pragma unroll
        for (int nt = 0; nt < 8; nt++) {
            int h = ng * 64 + nt * 8 + hq;
            float bv0 = __ldg(bias + h), bv1 = __ldg(bias + h + 1);
            int j = (L == 0) ? h : (L == 1) ? 128 + h : 256 + h;
            float w0 = __ldg(fcW + j), w1 = __ldg(fcW + j + 1);
            float s0 = 0.0f, s1 = 0.0f;
#pragma unroll
            for (int mt = 0; mt < 4; mt++) {
                s0 += fmaxf(acc[mt][nt][0] + bv0, 0.f) + fmaxf(acc[mt][nt][2] + bv0, 0.f);
                s1 += fmaxf(acc[mt][nt][1] + bv1, 0.f) + fmaxf(acc[mt][nt][3] + bv1, 0.f);
            }
            p += s0 * w0 + s1 * w1;
        }
#pragma unroll
        for (int o = 16; o > 0; o >>= 1) p += __shfl_xor_sync(0xFFFFFFFFu, p, o);
        if (lane == 0) atomicAdd(out + b, p);
    }
    if (L < 2 && ng >= 2) {
        float* yo = (L == 0 ? g_h0 : g_h1) + (size_t)b * 8192;
#pragma unroll
        for (int mt = 0; mt < 4; mt++) {
            int d = mt * 16 + dq;
#pragma unroll
            for (int nt = 0; nt < 8; nt++) {
                int h = ng * 64 + nt * 8 + hq;
                float bv0 = __ldg(bias + h), bv1 = __ldg(bias + h + 1);
                int n = h - 128;
                yo[(size_t)n * 64 + d]           = fmaxf(acc[mt][nt][0] + bv0, 0.f);
                yo[(size_t)(n + 1) * 64 + d]     = fmaxf(acc[mt][nt][1] + bv1, 0.f);
                yo[(size_t)n * 64 + d + 8]       = fmaxf(acc[mt][nt][2] + bv0, 0.f);
                yo[(size_t)(n + 1) * 64 + d + 8] = fmaxf(acc[mt][nt][3] + bv1, 0.f);
            }
        }
    }
}

extern "C" void kernel_launch(void* const* d_in, const int* in_sizes, int n_in,
                              void* d_out, int out_size) {
    const float* x   = (const float*)d_in[0];
    const float* W0  = (const float*)d_in[1];
    const float* b0  = (const float*)d_in[2];
    const float* W1  = (const float*)d_in[3];
    const float* b1  = (const float*)d_in[4];
    const float* W2  = (const float*)d_in[5];
    const float* b2  = (const float*)d_in[6];
    const float* fcW = (const float*)d_in[7];
    const float* fcb = (const float*)d_in[8];
    float* out = (float*)d_out;

    constexpr int SMEMSZ = 1024 + 1024 + 4 * 49152;   // pad + mbar header + 4 stages
    cudaFuncSetAttribute(cin_layer<0>, cudaFuncAttributeMaxDynamicSharedMemorySize, SMEMSZ);
    cudaFuncSetAttribute(cin_layer<1>, cudaFuncAttributeMaxDynamicSharedMemorySize, SMEMSZ);
    cudaFuncSetAttribute(cin_layer<2>, cudaFuncAttributeMaxDynamicSharedMemorySize, SMEMSZ);

    __half *wt0p, *wt1p, *wt2p;
    cudaGetSymbolAddress((void**)&wt0p, g_wt0);
    cudaGetSymbolAddress((void**)&wt1p, g_wt1);
    cudaGetSymbolAddress((void**)&wt2p, g_wt2);

    wtrans<32>  <<<16, 256>>>(W0, wt0p);
    wtrans<128> <<<64, 256>>>(W1, wt1p);
    wtrans<128> <<<64, 256>>>(W2, wt2p);
    init_out<<<4, 256>>>(fcb, out);

    cin_layer<0><<<512, 320, SMEMSZ>>>(x, b0, fcW, out);
    cin_layer<1><<<512, 320, SMEMSZ>>>(x, b1, fcW, out);
    cin_layer<2><<<512, 320, SMEMSZ>>>(x, b2, fcW, out);
}